// round 15
// baseline (speedup 1.0000x reference)
#include <cuda_runtime.h>
#include <cuda_bf16.h>
#include <stdint.h>

// Problem constants
#define BB   32
#define DD   256
#define TT   2048
#define KK   1024
#define NVEC (BB * TT)          // 65536 vectors
#define QOUT (BB * DD * TT)     // 16777216 quantized elements

#define MARGINF 1e-3f
#define GAPTHR  6e-4f

// ---------------------------------------------------------------------------
// Scratch (device globals; no allocations allowed)
// ---------------------------------------------------------------------------
__device__ __nv_bfloat16 g_xb[(size_t)NVEC * DD];   // x bf16, [n][d]
__device__ float         g_xT[(size_t)NVEC * DD];   // x f32 transposed, [n][d]
__device__ __nv_bfloat16 g_wb[(size_t)KK * DD];     // weight bf16, [k][d]
__device__ float         g_s2[KK];                  // exact ||w_k||^2
__device__ float         g_s2p[KK];                 // s2 + 2.0f (selection bias)
__device__ unsigned short g_cand[(size_t)NVEC * 64];
__device__ int           g_fast[NVEC];              // fast-path idx, or -1
__device__ int           g_idx[NVEC];

// ---------------------------------------------------------------------------
// Arch-portable PTX helpers (all base-target sm_80+ instructions)
// ---------------------------------------------------------------------------
__device__ __forceinline__ uint32_t smem_to_u32(const void* p) {
    uint32_t a;
    asm("{ .reg .u64 t; cvta.to.shared.u64 t, %1; cvt.u32.u64 %0, t; }"
        : "=r"(a) : "l"(p));
    return a;
}
__device__ __forceinline__ void ldsm4(uint32_t* r, uint32_t addr) {
    asm volatile("ldmatrix.sync.aligned.m8n8.x4.shared.b16 {%0,%1,%2,%3}, [%4];"
                 : "=r"(r[0]), "=r"(r[1]), "=r"(r[2]), "=r"(r[3]) : "r"(addr));
}
__device__ __forceinline__ void mma16816(float* d, const uint32_t* a,
                                         uint32_t b0, uint32_t b1) {
    asm volatile(
        "mma.sync.aligned.m16n8k16.row.col.f32.bf16.bf16.f32 "
        "{%0,%1,%2,%3}, {%4,%5,%6,%7}, {%8,%9}, {%0,%1,%2,%3};"
        : "+f"(d[0]), "+f"(d[1]), "+f"(d[2]), "+f"(d[3])
        : "r"(a[0]), "r"(a[1]), "r"(a[2]), "r"(a[3]), "r"(b0), "r"(b1));
}
__device__ __forceinline__ void cp16(uint32_t saddr, const void* g) {
    asm volatile("cp.async.cg.shared.global [%0], [%1], 16;"
                 :: "r"(saddr), "l"(g) : "memory");
}
#define CP_COMMIT() asm volatile("cp.async.commit_group;" ::: "memory")
#define CP_WAIT0()  asm volatile("cp.async.wait_group 0;" ::: "memory")

// two-min update on packed (float_bits<<32 | k) keys
#define TWOMIN(key, K1, K2) do { \
    unsigned long long _k = (key); \
    if (_k < (K1)) { (K2) = (K1); (K1) = _k; } \
    else if (_k < (K2)) { (K2) = _k; } \
} while (0)

// ---------------------------------------------------------------------------
// K0: transpose + convert. inputs[b][d][t] f32 -> g_xT[n][d] f32, g_xb[n][d] bf16
// ---------------------------------------------------------------------------
__global__ void vq_prep_x_kernel(const float* __restrict__ inputs) {
    __shared__ float tile[32][33];
    int t0 = blockIdx.x * 32;
    int d0 = blockIdx.y * 32;
    int b  = blockIdx.z;
    int tx = threadIdx.x;        // 0..31
    int ty = threadIdx.y;        // 0..7
    const float* in = inputs + (size_t)b * DD * TT;
    #pragma unroll
    for (int i = 0; i < 4; i++) {
        int d = d0 + ty + i * 8;
        tile[ty + i * 8][tx] = in[(size_t)d * TT + t0 + tx];
    }
    __syncthreads();
    #pragma unroll
    for (int i = 0; i < 4; i++) {
        int t = t0 + ty + i * 8;
        size_t n = (size_t)b * TT + t;
        float v = tile[tx][ty + i * 8];
        g_xT[n * DD + d0 + tx] = v;
        g_xb[n * DD + d0 + tx] = __float2bfloat16(v);
    }
}

// ---------------------------------------------------------------------------
// K1: weight bf16 + exact s2 (d-sequential fp32) + s2p
// ---------------------------------------------------------------------------
__global__ void vq_prep_w_kernel(const float* __restrict__ w) {
    int k = blockIdx.x * blockDim.x + threadIdx.x;
    if (k < KK) {
        const float* row = w + (size_t)k * DD;
        float s = 0.0f;
        #pragma unroll 8
        for (int d = 0; d < DD; d++) {
            float v = row[d];
            s = fmaf(v, v, s);
            g_wb[(size_t)k * DD + d] = __float2bfloat16(v);
        }
        g_s2[k]  = s;
        g_s2p[k] = s + 2.0f;
    }
}

// ---------------------------------------------------------------------------
// K2: mma.sync bf16 GEMM (128 vec x 1024 codes, K=256) + margin candidates
// + exact two-min tracking over ALL codes -> fast-path decision:
//   gap(second - first selection score) > GAPTHR  =>  argmin is decided here.
// Running-min threshold emission; 8 slots; overflow -> 0xFFFE sentinel.
// smem: A 64KB | B db 2x64KB | s2p 4KB | twomin 4KB
// ---------------------------------------------------------------------------
#define AS_OFF  0
#define BS_OFF  65536
#define S2P_OFF 196608
#define FST_OFF 200704
#define SMEM_BYTES 204800

__global__ void __launch_bounds__(256, 1)
vq_select_kernel() {
    extern __shared__ __align__(128) char smem[];
    uint32_t su = smem_to_u32(smem);
    float* s2p_s = (float*)(smem + S2P_OFF);

    const int tid    = threadIdx.x;
    const int lane   = tid & 31;
    const int wid    = tid >> 5;
    const int m_sub  = wid & 3;
    const int n_half = wid >> 2;
    const int m0w    = m_sub * 32;
    const int n0w    = n_half * 64;
    const int m0     = blockIdx.x * 128;

    // ---- load A tile: 128 rows x 256 bf16, swizzled ----
    {
        const uint4* src = (const uint4*)g_xb + (size_t)m0 * 32;
        #pragma unroll
        for (int it = 0; it < 16; it++) {
            int idx = tid + it * 256;
            int row = idx >> 5, c = idx & 31;
            *(uint4*)(smem + AS_OFF + row * 512 + ((c ^ (row & 7)) << 4)) = src[idx];
        }
    }
    // ---- load s2p (all 1024) ----
    ((float4*)(smem + S2P_OFF))[tid] = ((const float4*)g_s2p)[tid];

    // ---- B chunk 0 via cp.async ----
    {
        uint32_t dstb = su + BS_OFF;
        const uint4* src = (const uint4*)g_wb;
        #pragma unroll
        for (int it = 0; it < 16; it++) {
            int idx = tid + it * 256;
            int row = idx >> 5, c = idx & 31;
            cp16(dstb + row * 512 + ((c ^ (row & 7)) << 4), src + idx);
        }
    }
    CP_COMMIT();
    CP_WAIT0();
    __syncthreads();

    // ---- per-lane ldmatrix row bases ----
    const int grp = lane >> 3, r = lane & 7;
    uint32_t a_base[2]; int a_rm[2];
    #pragma unroll
    for (int mt = 0; mt < 2; mt++) {
        int row = m0w + mt * 16 + (grp & 1) * 8 + r;
        a_base[mt] = su + AS_OFF + row * 512;
        a_rm[mt]   = row & 7;
    }
    uint32_t b_base[4]; int b_rm[4];
    #pragma unroll
    for (int nt2 = 0; nt2 < 4; nt2++) {
        int row = n0w + nt2 * 16 + (grp >> 1) * 8 + r;
        b_base[nt2] = su + BS_OFF + row * 512;   // + buf*65536 at use
        b_rm[nt2]   = row & 7;
    }

    // candidate state + exact two-min keys per [mt][halfrow]
    unsigned long long cw0[2][2], cw1[2][2];
    unsigned long long t1[2][2], t2[2][2];
    int  cnt[2][2];
    int  ovf[2][2];
    float runmn[2][2];
    #pragma unroll
    for (int a = 0; a < 2; a++)
        #pragma unroll
        for (int b = 0; b < 2; b++) {
            cw0[a][b] = ~0ull; cw1[a][b] = ~0ull;
            t1[a][b] = ~0ull;  t2[a][b] = ~0ull;
            cnt[a][b] = 0; ovf[a][b] = 0; runmn[a][b] = 1e30f;
        }

    for (int nc = 0; nc < 8; nc++) {
        const int buf = nc & 1;

        // prefetch next B chunk into other buffer
        if (nc < 7) {
            uint32_t dstb = su + BS_OFF + (buf ^ 1) * 65536;
            const uint4* src = (const uint4*)g_wb + (size_t)(nc + 1) * 128 * 32;
            #pragma unroll
            for (int it = 0; it < 16; it++) {
                int idx = tid + it * 256;
                int row = idx >> 5, c = idx & 31;
                cp16(dstb + row * 512 + ((c ^ (row & 7)) << 4), src + idx);
            }
            CP_COMMIT();
        }

        // ---- GEMM: warp tile 32x64, K=256 ----
        float acc[2][8][4];
        #pragma unroll
        for (int mt = 0; mt < 2; mt++)
            #pragma unroll
            for (int nt = 0; nt < 8; nt++)
                #pragma unroll
                for (int j = 0; j < 4; j++) acc[mt][nt][j] = 0.0f;

        const uint32_t bufofs = buf * 65536;
        #pragma unroll 4
        for (int ks = 0; ks < 16; ks++) {
            uint32_t a_[2][4];
            #pragma unroll
            for (int mt = 0; mt < 2; mt++) {
                int c = ks * 2 + (grp >> 1);
                ldsm4(a_[mt], a_base[mt] + ((c ^ a_rm[mt]) << 4));
            }
            uint32_t b_[4][4];
            #pragma unroll
            for (int nt2 = 0; nt2 < 4; nt2++) {
                int c = ks * 2 + (grp & 1);
                ldsm4(b_[nt2], b_base[nt2] + bufofs + ((c ^ b_rm[nt2]) << 4));
            }
            #pragma unroll
            for (int mt = 0; mt < 2; mt++)
                #pragma unroll
                for (int nt2 = 0; nt2 < 4; nt2++) {
                    mma16816(acc[mt][2 * nt2 + 0], a_[mt], b_[nt2][0], b_[nt2][1]);
                    mma16816(acc[mt][2 * nt2 + 1], a_[mt], b_[nt2][2], b_[nt2][3]);
                }
        }

        // ---- epilogue ----
        const int ncb = nc * 128;
        float sp0[8], sp1[8];
        #pragma unroll
        for (int nt = 0; nt < 8; nt++) {
            int kk = ncb + n0w + nt * 8 + ((lane & 3) << 1);
            sp0[nt] = s2p_s[kk];
            sp1[nt] = s2p_s[kk + 1];
        }

        #pragma unroll
        for (int mt = 0; mt < 2; mt++) {
            float mn0 = 1e30f, mn1 = 1e30f;
            #pragma unroll
            for (int nt = 0; nt < 8; nt++) {
                int kk = ncb + n0w + nt * 8 + ((lane & 3) << 1);
                float s00 = fmaf(-2.0f, acc[mt][nt][0], sp0[nt]);
                float s01 = fmaf(-2.0f, acc[mt][nt][1], sp1[nt]);
                float s10 = fmaf(-2.0f, acc[mt][nt][2], sp0[nt]);
                float s11 = fmaf(-2.0f, acc[mt][nt][3], sp1[nt]);
                mn0 = fminf(mn0, fminf(s00, s01));
                mn1 = fminf(mn1, fminf(s10, s11));
                // exact two-min tracking (packed positive-float keys)
                unsigned long long k00 =
                    ((unsigned long long)__float_as_uint(s00) << 32) | (unsigned)kk;
                unsigned long long k01 =
                    ((unsigned long long)__float_as_uint(s01) << 32) | (unsigned)(kk + 1);
                unsigned long long k10 =
                    ((unsigned long long)__float_as_uint(s10) << 32) | (unsigned)kk;
                unsigned long long k11 =
                    ((unsigned long long)__float_as_uint(s11) << 32) | (unsigned)(kk + 1);
                TWOMIN(k00, t1[mt][0], t2[mt][0]);
                TWOMIN(k01, t1[mt][0], t2[mt][0]);
                TWOMIN(k10, t1[mt][1], t2[mt][1]);
                TWOMIN(k11, t1[mt][1], t2[mt][1]);
            }
            mn0 = fminf(mn0, __shfl_xor_sync(0xffffffffu, mn0, 1));
            mn0 = fminf(mn0, __shfl_xor_sync(0xffffffffu, mn0, 2));
            mn1 = fminf(mn1, __shfl_xor_sync(0xffffffffu, mn1, 1));
            mn1 = fminf(mn1, __shfl_xor_sync(0xffffffffu, mn1, 2));
            runmn[mt][0] = fminf(runmn[mt][0], mn0);
            runmn[mt][1] = fminf(runmn[mt][1], mn1);
            float thr0 = runmn[mt][0] + MARGINF;
            float thr1 = runmn[mt][1] + MARGINF;

            #pragma unroll
            for (int nt = 0; nt < 8; nt++) {
                int kk = ncb + n0w + nt * 8 + ((lane & 3) << 1);
                float s00 = fmaf(-2.0f, acc[mt][nt][0], sp0[nt]);
                float s01 = fmaf(-2.0f, acc[mt][nt][1], sp1[nt]);
                float s10 = fmaf(-2.0f, acc[mt][nt][2], sp0[nt]);
                float s11 = fmaf(-2.0f, acc[mt][nt][3], sp1[nt]);

                #pragma unroll
                for (int e = 0; e < 2; e++) {
                    float sv = (e == 0) ? s00 : s01;
                    int   kv = kk + e;
                    if (sv <= thr0) {
                        int c = cnt[mt][0];
                        unsigned long long up =
                            (unsigned long long)(0xFFFFu ^ (unsigned)kv) << ((c & 3) * 16);
                        if (c < 4)      cw0[mt][0] ^= up;
                        else if (c < 8) cw1[mt][0] ^= up;
                        else            ovf[mt][0] = 1;
                        cnt[mt][0] = c + 1;
                    }
                }
                #pragma unroll
                for (int e = 0; e < 2; e++) {
                    float sv = (e == 0) ? s10 : s11;
                    int   kv = kk + e;
                    if (sv <= thr1) {
                        int c = cnt[mt][1];
                        unsigned long long up =
                            (unsigned long long)(0xFFFFu ^ (unsigned)kv) << ((c & 3) * 16);
                        if (c < 4)      cw0[mt][1] ^= up;
                        else if (c < 8) cw1[mt][1] ^= up;
                        else            ovf[mt][1] = 1;
                        cnt[mt][1] = c + 1;
                    }
                }
            }
        }

        if (nc < 7) CP_WAIT0();
        __syncthreads();   // all warps done reading buf before it is refilled
    }

    // ---- quad-merge the two-min keys across lanes (xor 1, 2) ----
    #pragma unroll
    for (int mt = 0; mt < 2; mt++)
        #pragma unroll
        for (int h = 0; h < 2; h++) {
            unsigned long long a1 = t1[mt][h], a2 = t2[mt][h];
            #pragma unroll
            for (int off = 1; off <= 2; off <<= 1) {
                unsigned long long b1 = __shfl_xor_sync(0xffffffffu, a1, off);
                unsigned long long b2 = __shfl_xor_sync(0xffffffffu, a2, off);
                unsigned long long n1 = (a1 < b1) ? a1 : b1;
                unsigned long long mx = (a1 < b1) ? b1 : a1;
                unsigned long long n2 = (a2 < b2) ? a2 : b2;
                a1 = n1;
                a2 = (mx < n2) ? mx : n2;
            }
            t1[mt][h] = a1; t2[mt][h] = a2;
        }

    // stage per-half two-mins to smem
    {
        ulonglong2* sm2 = (ulonglong2*)(smem + FST_OFF);
        if ((lane & 3) == 0) {
            #pragma unroll
            for (int mt = 0; mt < 2; mt++)
                #pragma unroll
                for (int h = 0; h < 2; h++) {
                    int vl = m0w + mt * 16 + (lane >> 2) + h * 8;
                    ulonglong2 st; st.x = t1[mt][h]; st.y = t2[mt][h];
                    sm2[vl * 2 + n_half] = st;
                }
        }
    }

    // ---- write candidate slots: 64 ushort per vector ----
    #pragma unroll
    for (int mt = 0; mt < 2; mt++)
        #pragma unroll
        for (int h = 0; h < 2; h++) {
            int v = m0 + m0w + mt * 16 + (lane >> 2) + h * 8;
            unsigned long long a0 = cw0[mt][h];
            unsigned long long a1 = cw1[mt][h];
            if (ovf[mt][h])
                a1 = (a1 & 0x0000FFFFFFFFFFFFull) | (0xFFFEull << 48);
            size_t base = (size_t)v * 64 + n_half * 32 + (lane & 3) * 8;
            ulonglong2 st; st.x = a0; st.y = a1;
            *(ulonglong2*)(g_cand + base) = st;
        }

    __syncthreads();

    // ---- fast-path decision: merge halves, compute gap ----
    if (tid < 128) {
        const ulonglong2* sm2 = (const ulonglong2*)(smem + FST_OFF);
        ulonglong2 A = sm2[tid * 2 + 0];
        ulonglong2 B = sm2[tid * 2 + 1];
        unsigned long long g1 = (A.x < B.x) ? A.x : B.x;
        unsigned long long mx = (A.x < B.x) ? B.x : A.x;
        unsigned long long mn2 = (A.y < B.y) ? A.y : B.y;
        unsigned long long g2 = (mx < mn2) ? mx : mn2;
        float gap = __uint_as_float((unsigned)(g2 >> 32))
                  - __uint_as_float((unsigned)(g1 >> 32));
        int idx = (int)(g1 & 0xFFFFFFFFull);
        if (gap > GAPTHR) {
            g_idx[m0 + tid]  = idx;
            g_fast[m0 + tid] = idx;
        } else {
            g_fast[m0 + tid] = -1;
        }
    }
}

// ---------------------------------------------------------------------------
// K3: exact fp32 rescore, warp-per-vector. Fast-path vectors exit immediately
// (select already proved + wrote the argmin). Slow path: bit-identical
// arithmetic to round 1 (d-ASCENDING fp32 FMA; dist = fmaf(-2, m, s1 + s2);
// u64 tie-break to lowest k), xr staged in smem, ballot-compacted candidates.
// Overflow sentinel 0xFFFE -> lane-parallel exact full scan. Fused idx output.
// ---------------------------------------------------------------------------
__global__ void __launch_bounds__(256, 8)
vq_rescore_kernel(const float* __restrict__ weight,
                  float* __restrict__ out_idx, int write_idx) {
    __shared__ float xs[8][DD];
    __shared__ unsigned short clist[8][72];

    const int wslot = threadIdx.x >> 5;
    const int lane  = threadIdx.x & 31;
    const int n     = blockIdx.x * 8 + wslot;

    // ---- fast path: decided in select ----
    int f = g_fast[n];
    if (f >= 0) {
        if (lane == 0 && write_idx) out_idx[n] = (float)f;
        return;
    }

    // ---- stage xr into smem (coalesced float4) ----
    float* xsw = xs[wslot];
    {
        const float4* xr4 = (const float4*)(g_xT + (size_t)n * DD);
        ((float4*)xsw)[lane]      = xr4[lane];
        ((float4*)xsw)[lane + 32] = xr4[lane + 32];
    }

    // ---- read + compact candidates ----
    unsigned short c0 = g_cand[(size_t)n * 64 + lane];
    unsigned short c1 = g_cand[(size_t)n * 64 + 32 + lane];
    bool fb = __any_sync(0xffffffffu, (c0 == 0xFFFE) || (c1 == 0xFFFE));
    unsigned lt = (1u << lane) - 1u;
    unsigned mk0 = __ballot_sync(0xffffffffu, c0 < KK);
    unsigned mk1 = __ballot_sync(0xffffffffu, c1 < KK);
    int base1 = __popc(mk0);
    if (c0 < KK) clist[wslot][__popc(mk0 & lt)] = c0;
    if (c1 < KK) clist[wslot][base1 + __popc(mk1 & lt)] = c1;
    int C = base1 + __popc(mk1);
    __syncwarp();

    // ---- s1: d-ascending fp32 FMA from smem (LDS broadcast) ----
    float s1 = 0.0f;
    #pragma unroll 16
    for (int q = 0; q < DD / 4; q++) {
        float4 xq = ((const float4*)xsw)[q];
        s1 = fmaf(xq.x, xq.x, s1);
        s1 = fmaf(xq.y, xq.y, s1);
        s1 = fmaf(xq.z, xq.z, s1);
        s1 = fmaf(xq.w, xq.w, s1);
    }

    unsigned long long best = ~0ull;
    if (!fb) {
        for (int cb = lane; cb < C; cb += 32) {
            unsigned ks = clist[wslot][cb];
            const float4* wr4 = (const float4*)(weight + (size_t)ks * DD);
            float m = 0.0f;
            #pragma unroll 16
            for (int q = 0; q < DD / 4; q++) {
                float4 xq = ((const float4*)xsw)[q];
                float4 wq = wr4[q];
                m = fmaf(xq.x, wq.x, m);
                m = fmaf(xq.y, wq.y, m);
                m = fmaf(xq.z, wq.z, m);
                m = fmaf(xq.w, wq.w, m);
            }
            float dist = fmaf(-2.0f, m, s1 + g_s2[ks]);
            unsigned long long key =
                ((unsigned long long)__float_as_uint(dist) << 32) | ks;
            if (key < best) best = key;
        }
    } else {
        // exact full scan: lane handles codes lane, lane+32, ...
        for (int i = 0; i < 32; i++) {
            unsigned ks = (unsigned)(lane + i * 32);
            const float4* wr4 = (const float4*)(weight + (size_t)ks * DD);
            float m = 0.0f;
            #pragma unroll 16
            for (int q = 0; q < DD / 4; q++) {
                float4 xq = ((const float4*)xsw)[q];
                float4 wq = wr4[q];
                m = fmaf(xq.x, wq.x, m);
                m = fmaf(xq.y, wq.y, m);
                m = fmaf(xq.z, wq.z, m);
                m = fmaf(xq.w, wq.w, m);
            }
            float dist = fmaf(-2.0f, m, s1 + g_s2[ks]);
            unsigned long long key =
                ((unsigned long long)__float_as_uint(dist) << 32) | ks;
            if (key < best) best = key;
        }
    }

    #pragma unroll
    for (int off = 16; off > 0; off >>= 1) {
        unsigned long long o = __shfl_xor_sync(0xffffffffu, best, off);
        if (o < best) best = o;
    }
    if (lane == 0) {
        int idx = (int)(best & 0xFFFFFFFFull);
        g_idx[n] = idx;
        if (write_idx) out_idx[n] = (float)idx;
    }
}

// ---------------------------------------------------------------------------
// K4: gather quantized output. out[b, d, t] = weight[idx[b*TT+t], d]
// ---------------------------------------------------------------------------
__global__ void vq_gather_kernel(const float* __restrict__ weight,
                                 float* __restrict__ out) {
    int gid = blockIdx.x * blockDim.x + threadIdx.x;
    const int T4 = TT / 4;
    if (gid >= BB * DD * T4) return;
    int t4  = gid % T4;
    int rem = gid / T4;
    int d   = rem % DD;
    int b   = rem / DD;
    int t   = t4 * 4;
    int base = b * TT + t;
    int i0 = g_idx[base + 0];
    int i1 = g_idx[base + 1];
    int i2 = g_idx[base + 2];
    int i3 = g_idx[base + 3];
    float4 o;
    o.x = weight[(size_t)i0 * DD + d];
    o.y = weight[(size_t)i1 * DD + d];
    o.z = weight[(size_t)i2 * DD + d];
    o.w = weight[(size_t)i3 * DD + d];
    *(float4*)&out[((size_t)b * DD + d) * TT + t] = o;
}

// ---------------------------------------------------------------------------
// Launch
// ---------------------------------------------------------------------------
extern "C" void kernel_launch(void* const* d_in, const int* in_sizes, int n_in,
                              void* d_out, int out_size) {
    const float* inputs = (const float*)d_in[0];
    const float* weight = (const float*)d_in[1];
    float* out = (float*)d_out;

    cudaFuncSetAttribute(vq_select_kernel,
                         cudaFuncAttributeMaxDynamicSharedMemorySize, SMEM_BYTES);

    dim3 pgrid(TT / 32, DD / 32, BB);
    dim3 pblk(32, 8);
    vq_prep_x_kernel<<<pgrid, pblk>>>(inputs);
    vq_prep_w_kernel<<<(KK + 255) / 256, 256>>>(weight);

    vq_select_kernel<<<NVEC / 128, 256, SMEM_BYTES>>>();

    int write_idx = (out_size >= QOUT + NVEC) ? 1 : 0;
    // warp per vector: 65536 warps = 8192 blocks x 8 warps
    vq_rescore_kernel<<<NVEC / 8, 256>>>(weight, out + QOUT, write_idx);

    int gthreads = BB * DD * (TT / 4);
    vq_gather_kernel<<<(gthreads + 255) / 256, 256>>>(weight, out);
}

// round 16
// speedup vs baseline: 1.1080x; 1.1080x over previous
#include <cuda_runtime.h>
#include <cuda_bf16.h>
#include <stdint.h>

// Problem constants
#define BB   32
#define DD   256
#define TT   2048
#define KK   1024
#define NVEC (BB * TT)          // 65536 vectors
#define QOUT (BB * DD * TT)     // 16777216 quantized elements

#define MARGINF 1.25e-3f        // emission margin on quantized row-min
#define GAPTHR  8e-4f           // fast-path gap threshold (quantized floats)

// ---------------------------------------------------------------------------
// Scratch (device globals; no allocations allowed)
// ---------------------------------------------------------------------------
__device__ __nv_bfloat16 g_xb[(size_t)NVEC * DD];   // x bf16, [n][d]
__device__ __nv_bfloat16 g_wb[(size_t)KK * DD];     // weight bf16, [k][d]
__device__ float         g_s2[KK];                  // exact ||w_k||^2
__device__ float         g_s2p[KK];                 // s2 + 2.0f (selection bias)
__device__ unsigned short g_cand[(size_t)NVEC * 64];
__device__ int           g_fast[NVEC];              // fast-path idx, or -1
__device__ int           g_idx[NVEC];

// ---------------------------------------------------------------------------
// Arch-portable PTX helpers (all base-target sm_80+ instructions)
// ---------------------------------------------------------------------------
__device__ __forceinline__ uint32_t smem_to_u32(const void* p) {
    uint32_t a;
    asm("{ .reg .u64 t; cvta.to.shared.u64 t, %1; cvt.u32.u64 %0, t; }"
        : "=r"(a) : "l"(p));
    return a;
}
__device__ __forceinline__ void ldsm4(uint32_t* r, uint32_t addr) {
    asm volatile("ldmatrix.sync.aligned.m8n8.x4.shared.b16 {%0,%1,%2,%3}, [%4];"
                 : "=r"(r[0]), "=r"(r[1]), "=r"(r[2]), "=r"(r[3]) : "r"(addr));
}
__device__ __forceinline__ void mma16816(float* d, const uint32_t* a,
                                         uint32_t b0, uint32_t b1) {
    asm volatile(
        "mma.sync.aligned.m16n8k16.row.col.f32.bf16.bf16.f32 "
        "{%0,%1,%2,%3}, {%4,%5,%6,%7}, {%8,%9}, {%0,%1,%2,%3};"
        : "+f"(d[0]), "+f"(d[1]), "+f"(d[2]), "+f"(d[3])
        : "r"(a[0]), "r"(a[1]), "r"(a[2]), "r"(a[3]), "r"(b0), "r"(b1));
}
__device__ __forceinline__ void cp16(uint32_t saddr, const void* g) {
    asm volatile("cp.async.cg.shared.global [%0], [%1], 16;"
                 :: "r"(saddr), "l"(g) : "memory");
}
#define CP_COMMIT() asm volatile("cp.async.commit_group;" ::: "memory")
#define CP_WAIT0()  asm volatile("cp.async.wait_group 0;" ::: "memory")

// pack selection score + index into order-preserving u32 key
__device__ __forceinline__ unsigned packkey(float s, int k) {
    return (__float_as_uint(s) & 0xFFFFFC00u) | (unsigned)k;
}
// branch-free two-min update (3 ops)
#define TWOMIN3(k, K1, K2) do { \
    unsigned _k = (k); \
    unsigned _mx = max((K1), _k); \
    (K1) = min((K1), _k); \
    (K2) = min((K2), _mx); \
} while (0)

// ---------------------------------------------------------------------------
// K0: transpose + convert. inputs[b][d][t] f32 -> g_xb[n][d] bf16
// ---------------------------------------------------------------------------
__global__ void vq_prep_x_kernel(const float* __restrict__ inputs) {
    __shared__ float tile[32][33];
    int t0 = blockIdx.x * 32;
    int d0 = blockIdx.y * 32;
    int b  = blockIdx.z;
    int tx = threadIdx.x;        // 0..31
    int ty = threadIdx.y;        // 0..7
    const float* in = inputs + (size_t)b * DD * TT;
    #pragma unroll
    for (int i = 0; i < 4; i++) {
        int d = d0 + ty + i * 8;
        tile[ty + i * 8][tx] = in[(size_t)d * TT + t0 + tx];
    }
    __syncthreads();
    #pragma unroll
    for (int i = 0; i < 4; i++) {
        int t = t0 + ty + i * 8;
        size_t n = (size_t)b * TT + t;
        g_xb[n * DD + d0 + tx] = __float2bfloat16(tile[tx][ty + i * 8]);
    }
}

// ---------------------------------------------------------------------------
// K1: weight bf16 + exact s2 (d-sequential fp32) + s2p
// ---------------------------------------------------------------------------
__global__ void vq_prep_w_kernel(const float* __restrict__ w) {
    int k = blockIdx.x * blockDim.x + threadIdx.x;
    if (k < KK) {
        const float* row = w + (size_t)k * DD;
        float s = 0.0f;
        #pragma unroll 8
        for (int d = 0; d < DD; d++) {
            float v = row[d];
            s = fmaf(v, v, s);
            g_wb[(size_t)k * DD + d] = __float2bfloat16(v);
        }
        g_s2[k]  = s;
        g_s2p[k] = s + 2.0f;
    }
}

// ---------------------------------------------------------------------------
// K2: mma.sync bf16 GEMM (128 vec x 1024 codes, K=256) + margin candidates
// + packed-u32 two-min tracking -> fast-path decision (gap > GAPTHR).
// Running-min threshold emission; 8 slots; overflow -> 0xFFFE sentinel.
// smem: A 64KB | B db 2x64KB | s2p 4KB | twomin 2KB
// ---------------------------------------------------------------------------
#define AS_OFF  0
#define BS_OFF  65536
#define S2P_OFF 196608
#define FST_OFF 200704
#define SMEM_BYTES 202752

__global__ void __launch_bounds__(256, 1)
vq_select_kernel() {
    extern __shared__ __align__(128) char smem[];
    uint32_t su = smem_to_u32(smem);
    float* s2p_s = (float*)(smem + S2P_OFF);

    const int tid    = threadIdx.x;
    const int lane   = tid & 31;
    const int wid    = tid >> 5;
    const int m_sub  = wid & 3;
    const int n_half = wid >> 2;
    const int m0w    = m_sub * 32;
    const int n0w    = n_half * 64;
    const int m0     = blockIdx.x * 128;

    // ---- load A tile: 128 rows x 256 bf16, swizzled ----
    {
        const uint4* src = (const uint4*)g_xb + (size_t)m0 * 32;
        #pragma unroll
        for (int it = 0; it < 16; it++) {
            int idx = tid + it * 256;
            int row = idx >> 5, c = idx & 31;
            *(uint4*)(smem + AS_OFF + row * 512 + ((c ^ (row & 7)) << 4)) = src[idx];
        }
    }
    // ---- load s2p (all 1024) ----
    ((float4*)(smem + S2P_OFF))[tid] = ((const float4*)g_s2p)[tid];

    // ---- B chunk 0 via cp.async ----
    {
        uint32_t dstb = su + BS_OFF;
        const uint4* src = (const uint4*)g_wb;
        #pragma unroll
        for (int it = 0; it < 16; it++) {
            int idx = tid + it * 256;
            int row = idx >> 5, c = idx & 31;
            cp16(dstb + row * 512 + ((c ^ (row & 7)) << 4), src + idx);
        }
    }
    CP_COMMIT();
    CP_WAIT0();
    __syncthreads();

    // ---- per-lane ldmatrix row bases ----
    const int grp = lane >> 3, r = lane & 7;
    uint32_t a_base[2]; int a_rm[2];
    #pragma unroll
    for (int mt = 0; mt < 2; mt++) {
        int row = m0w + mt * 16 + (grp & 1) * 8 + r;
        a_base[mt] = su + AS_OFF + row * 512;
        a_rm[mt]   = row & 7;
    }
    uint32_t b_base[4]; int b_rm[4];
    #pragma unroll
    for (int nt2 = 0; nt2 < 4; nt2++) {
        int row = n0w + nt2 * 16 + (grp >> 1) * 8 + r;
        b_base[nt2] = su + BS_OFF + row * 512;   // + buf*65536 at use
        b_rm[nt2]   = row & 7;
    }

    // candidate state + packed two-min keys per [mt][halfrow]
    unsigned long long cw0[2][2], cw1[2][2];
    unsigned t1[2][2], t2[2][2];
    int  cnt[2][2];
    int  ovf[2][2];
    #pragma unroll
    for (int a = 0; a < 2; a++)
        #pragma unroll
        for (int b = 0; b < 2; b++) {
            cw0[a][b] = ~0ull; cw1[a][b] = ~0ull;
            t1[a][b] = 0xFFFFFFFFu; t2[a][b] = 0xFFFFFFFFu;
            cnt[a][b] = 0; ovf[a][b] = 0;
        }

    for (int nc = 0; nc < 8; nc++) {
        const int buf = nc & 1;

        // prefetch next B chunk into other buffer
        if (nc < 7) {
            uint32_t dstb = su + BS_OFF + (buf ^ 1) * 65536;
            const uint4* src = (const uint4*)g_wb + (size_t)(nc + 1) * 128 * 32;
            #pragma unroll
            for (int it = 0; it < 16; it++) {
                int idx = tid + it * 256;
                int row = idx >> 5, c = idx & 31;
                cp16(dstb + row * 512 + ((c ^ (row & 7)) << 4), src + idx);
            }
            CP_COMMIT();
        }

        // ---- GEMM: warp tile 32x64, K=256 ----
        float acc[2][8][4];
        #pragma unroll
        for (int mt = 0; mt < 2; mt++)
            #pragma unroll
            for (int nt = 0; nt < 8; nt++)
                #pragma unroll
                for (int j = 0; j < 4; j++) acc[mt][nt][j] = 0.0f;

        const uint32_t bufofs = buf * 65536;
        #pragma unroll 4
        for (int ks = 0; ks < 16; ks++) {
            uint32_t a_[2][4];
            #pragma unroll
            for (int mt = 0; mt < 2; mt++) {
                int c = ks * 2 + (grp >> 1);
                ldsm4(a_[mt], a_base[mt] + ((c ^ a_rm[mt]) << 4));
            }
            uint32_t b_[4][4];
            #pragma unroll
            for (int nt2 = 0; nt2 < 4; nt2++) {
                int c = ks * 2 + (grp & 1);
                ldsm4(b_[nt2], b_base[nt2] + bufofs + ((c ^ b_rm[nt2]) << 4));
            }
            #pragma unroll
            for (int mt = 0; mt < 2; mt++)
                #pragma unroll
                for (int nt2 = 0; nt2 < 4; nt2++) {
                    mma16816(acc[mt][2 * nt2 + 0], a_[mt], b_[nt2][0], b_[nt2][1]);
                    mma16816(acc[mt][2 * nt2 + 1], a_[mt], b_[nt2][2], b_[nt2][3]);
                }
        }

        // ---- epilogue ----
        const int ncb = nc * 128;
        float sp0[8], sp1[8];
        #pragma unroll
        for (int nt = 0; nt < 8; nt++) {
            int kk = ncb + n0w + nt * 8 + ((lane & 3) << 1);
            sp0[nt] = s2p_s[kk];
            sp1[nt] = s2p_s[kk + 1];
        }

        #pragma unroll
        for (int mt = 0; mt < 2; mt++) {
            // pass 1: packed two-min over my 8 columns (both row-halves)
            #pragma unroll
            for (int nt = 0; nt < 8; nt++) {
                int kk = ncb + n0w + nt * 8 + ((lane & 3) << 1);
                float s00 = fmaf(-2.0f, acc[mt][nt][0], sp0[nt]);
                float s01 = fmaf(-2.0f, acc[mt][nt][1], sp1[nt]);
                float s10 = fmaf(-2.0f, acc[mt][nt][2], sp0[nt]);
                float s11 = fmaf(-2.0f, acc[mt][nt][3], sp1[nt]);
                TWOMIN3(packkey(s00, kk),     t1[mt][0], t2[mt][0]);
                TWOMIN3(packkey(s01, kk + 1), t1[mt][0], t2[mt][0]);
                TWOMIN3(packkey(s10, kk),     t1[mt][1], t2[mt][1]);
                TWOMIN3(packkey(s11, kk + 1), t1[mt][1], t2[mt][1]);
            }
            // quad-merged row min (includes all chunks so far) -> thresholds
            unsigned r0 = t1[mt][0], r1 = t1[mt][1];
            r0 = min(r0, __shfl_xor_sync(0xffffffffu, r0, 1));
            r0 = min(r0, __shfl_xor_sync(0xffffffffu, r0, 2));
            r1 = min(r1, __shfl_xor_sync(0xffffffffu, r1, 1));
            r1 = min(r1, __shfl_xor_sync(0xffffffffu, r1, 2));
            float thr0 = __uint_as_float(r0 & 0xFFFFFC00u) + MARGINF;
            float thr1 = __uint_as_float(r1 & 0xFFFFFC00u) + MARGINF;

            // pass 2: margin emission
            #pragma unroll
            for (int nt = 0; nt < 8; nt++) {
                int kk = ncb + n0w + nt * 8 + ((lane & 3) << 1);
                float s00 = fmaf(-2.0f, acc[mt][nt][0], sp0[nt]);
                float s01 = fmaf(-2.0f, acc[mt][nt][1], sp1[nt]);
                float s10 = fmaf(-2.0f, acc[mt][nt][2], sp0[nt]);
                float s11 = fmaf(-2.0f, acc[mt][nt][3], sp1[nt]);

                #pragma unroll
                for (int e = 0; e < 2; e++) {
                    float sv = (e == 0) ? s00 : s01;
                    int   kv = kk + e;
                    if (sv <= thr0) {
                        int c = cnt[mt][0];
                        unsigned long long up =
                            (unsigned long long)(0xFFFFu ^ (unsigned)kv) << ((c & 3) * 16);
                        if (c < 4)      cw0[mt][0] ^= up;
                        else if (c < 8) cw1[mt][0] ^= up;
                        else            ovf[mt][0] = 1;
                        cnt[mt][0] = c + 1;
                    }
                }
                #pragma unroll
                for (int e = 0; e < 2; e++) {
                    float sv = (e == 0) ? s10 : s11;
                    int   kv = kk + e;
                    if (sv <= thr1) {
                        int c = cnt[mt][1];
                        unsigned long long up =
                            (unsigned long long)(0xFFFFu ^ (unsigned)kv) << ((c & 3) * 16);
                        if (c < 4)      cw0[mt][1] ^= up;
                        else if (c < 8) cw1[mt][1] ^= up;
                        else            ovf[mt][1] = 1;
                        cnt[mt][1] = c + 1;
                    }
                }
            }
        }

        if (nc < 7) CP_WAIT0();
        __syncthreads();   // all warps done reading buf before it is refilled
    }

    // ---- quad-merge the (t1,t2) pairs across lanes (xor 1, 2) ----
    #pragma unroll
    for (int mt = 0; mt < 2; mt++)
        #pragma unroll
        for (int h = 0; h < 2; h++) {
            unsigned a1 = t1[mt][h], a2 = t2[mt][h];
            #pragma unroll
            for (int off = 1; off <= 2; off <<= 1) {
                unsigned b1 = __shfl_xor_sync(0xffffffffu, a1, off);
                unsigned b2 = __shfl_xor_sync(0xffffffffu, a2, off);
                unsigned n1 = min(a1, b1);
                a2 = min(max(a1, b1), min(a2, b2));
                a1 = n1;
            }
            t1[mt][h] = a1; t2[mt][h] = a2;
        }

    // stage per-half two-mins to smem
    {
        uint2* sm2 = (uint2*)(smem + FST_OFF);
        if ((lane & 3) == 0) {
            #pragma unroll
            for (int mt = 0; mt < 2; mt++)
                #pragma unroll
                for (int h = 0; h < 2; h++) {
                    int vl = m0w + mt * 16 + (lane >> 2) + h * 8;
                    uint2 st; st.x = t1[mt][h]; st.y = t2[mt][h];
                    sm2[vl * 2 + n_half] = st;
                }
        }
    }

    // ---- write candidate slots: 64 ushort per vector ----
    #pragma unroll
    for (int mt = 0; mt < 2; mt++)
        #pragma unroll
        for (int h = 0; h < 2; h++) {
            int v = m0 + m0w + mt * 16 + (lane >> 2) + h * 8;
            unsigned long long a0 = cw0[mt][h];
            unsigned long long a1 = cw1[mt][h];
            if (ovf[mt][h])
                a1 = (a1 & 0x0000FFFFFFFFFFFFull) | (0xFFFEull << 48);
            size_t base = (size_t)v * 64 + n_half * 32 + (lane & 3) * 8;
            ulonglong2 st; st.x = a0; st.y = a1;
            *(ulonglong2*)(g_cand + base) = st;
        }

    __syncthreads();

    // ---- fast-path decision: merge halves, compute quantized gap ----
    if (tid < 128) {
        const uint2* sm2 = (const uint2*)(smem + FST_OFF);
        uint2 A = sm2[tid * 2 + 0];
        uint2 B = sm2[tid * 2 + 1];
        unsigned g1 = min(A.x, B.x);
        unsigned g2 = min(max(A.x, B.x), min(A.y, B.y));
        float gap = __uint_as_float(g2 & 0xFFFFFC00u)
                  - __uint_as_float(g1 & 0xFFFFFC00u);
        int idx = (int)(g1 & 0x3FFu);
        if (gap > GAPTHR) {
            g_idx[m0 + tid]  = idx;
            g_fast[m0 + tid] = idx;
        } else {
            g_fast[m0 + tid] = -1;
        }
    }
}

// ---------------------------------------------------------------------------
// K3: exact fp32 rescore, warp-per-vector. Fast-path vectors exit immediately.
// Slow path: bit-identical arithmetic to round 1 (d-ASCENDING fp32 FMA;
// dist = fmaf(-2, m, s1 + s2); u64 tie-break to lowest k). x staged into smem
// directly from the original inputs (identical bits to the old g_xT copy).
// Overflow sentinel 0xFFFE -> lane-parallel exact full scan. Fused idx output.
// ---------------------------------------------------------------------------
__global__ void __launch_bounds__(256, 8)
vq_rescore_kernel(const float* __restrict__ inputs,
                  const float* __restrict__ weight,
                  float* __restrict__ out_idx, int write_idx) {
    __shared__ float xs[8][DD];
    __shared__ unsigned short clist[8][72];

    const int wslot = threadIdx.x >> 5;
    const int lane  = threadIdx.x & 31;
    const int n     = blockIdx.x * 8 + wslot;

    // ---- fast path: decided in select ----
    int f = g_fast[n];
    if (f >= 0) {
        if (lane == 0 && write_idx) out_idx[n] = (float)f;
        return;
    }

    // ---- stage x into smem from inputs[b, :, t] (strided; exact f32 bits) ----
    float* xsw = xs[wslot];
    {
        const float* xin = inputs + (size_t)(n >> 11) * DD * TT + (n & (TT - 1));
        #pragma unroll
        for (int q = 0; q < 8; q++)
            xsw[lane + 32 * q] = xin[(size_t)(lane + 32 * q) * TT];
    }

    // ---- read + compact candidates ----
    unsigned short c0 = g_cand[(size_t)n * 64 + lane];
    unsigned short c1 = g_cand[(size_t)n * 64 + 32 + lane];
    bool fb = __any_sync(0xffffffffu, (c0 == 0xFFFE) || (c1 == 0xFFFE));
    unsigned lt = (1u << lane) - 1u;
    unsigned mk0 = __ballot_sync(0xffffffffu, c0 < KK);
    unsigned mk1 = __ballot_sync(0xffffffffu, c1 < KK);
    int base1 = __popc(mk0);
    if (c0 < KK) clist[wslot][__popc(mk0 & lt)] = c0;
    if (c1 < KK) clist[wslot][base1 + __popc(mk1 & lt)] = c1;
    int C = base1 + __popc(mk1);
    __syncwarp();

    // ---- s1: d-ascending fp32 FMA from smem (LDS broadcast) ----
    float s1 = 0.0f;
    #pragma unroll 16
    for (int q = 0; q < DD / 4; q++) {
        float4 xq = ((const float4*)xsw)[q];
        s1 = fmaf(xq.x, xq.x, s1);
        s1 = fmaf(xq.y, xq.y, s1);
        s1 = fmaf(xq.z, xq.z, s1);
        s1 = fmaf(xq.w, xq.w, s1);
    }

    unsigned long long best = ~0ull;
    if (!fb) {
        for (int cb = lane; cb < C; cb += 32) {
            unsigned ks = clist[wslot][cb];
            const float4* wr4 = (const float4*)(weight + (size_t)ks * DD);
            float m = 0.0f;
            #pragma unroll 16
            for (int q = 0; q < DD / 4; q++) {
                float4 xq = ((const float4*)xsw)[q];
                float4 wq = wr4[q];
                m = fmaf(xq.x, wq.x, m);
                m = fmaf(xq.y, wq.y, m);
                m = fmaf(xq.z, wq.z, m);
                m = fmaf(xq.w, wq.w, m);
            }
            float dist = fmaf(-2.0f, m, s1 + g_s2[ks]);
            unsigned long long key =
                ((unsigned long long)__float_as_uint(dist) << 32) | ks;
            if (key < best) best = key;
        }
    } else {
        // exact full scan: lane handles codes lane, lane+32, ...
        for (int i = 0; i < 32; i++) {
            unsigned ks = (unsigned)(lane + i * 32);
            const float4* wr4 = (const float4*)(weight + (size_t)ks * DD);
            float m = 0.0f;
            #pragma unroll 16
            for (int q = 0; q < DD / 4; q++) {
                float4 xq = ((const float4*)xsw)[q];
                float4 wq = wr4[q];
                m = fmaf(xq.x, wq.x, m);
                m = fmaf(xq.y, wq.y, m);
                m = fmaf(xq.z, wq.z, m);
                m = fmaf(xq.w, wq.w, m);
            }
            float dist = fmaf(-2.0f, m, s1 + g_s2[ks]);
            unsigned long long key =
                ((unsigned long long)__float_as_uint(dist) << 32) | ks;
            if (key < best) best = key;
        }
    }

    #pragma unroll
    for (int off = 16; off > 0; off >>= 1) {
        unsigned long long o = __shfl_xor_sync(0xffffffffu, best, off);
        if (o < best) best = o;
    }
    if (lane == 0) {
        int idx = (int)(best & 0xFFFFFFFFull);
        g_idx[n] = idx;
        if (write_idx) out_idx[n] = (float)idx;
    }
}

// ---------------------------------------------------------------------------
// K4: gather quantized output. out[b, d, t] = weight[idx[b*TT+t], d]
// ---------------------------------------------------------------------------
__global__ void vq_gather_kernel(const float* __restrict__ weight,
                                 float* __restrict__ out) {
    int gid = blockIdx.x * blockDim.x + threadIdx.x;
    const int T4 = TT / 4;
    if (gid >= BB * DD * T4) return;
    int t4  = gid % T4;
    int rem = gid / T4;
    int d   = rem % DD;
    int b   = rem / DD;
    int t   = t4 * 4;
    int base = b * TT + t;
    int i0 = g_idx[base + 0];
    int i1 = g_idx[base + 1];
    int i2 = g_idx[base + 2];
    int i3 = g_idx[base + 3];
    float4 o;
    o.x = weight[(size_t)i0 * DD + d];
    o.y = weight[(size_t)i1 * DD + d];
    o.z = weight[(size_t)i2 * DD + d];
    o.w = weight[(size_t)i3 * DD + d];
    *(float4*)&out[((size_t)b * DD + d) * TT + t] = o;
}

// ---------------------------------------------------------------------------
// Launch
// ---------------------------------------------------------------------------
extern "C" void kernel_launch(void* const* d_in, const int* in_sizes, int n_in,
                              void* d_out, int out_size) {
    const float* inputs = (const float*)d_in[0];
    const float* weight = (const float*)d_in[1];
    float* out = (float*)d_out;

    cudaFuncSetAttribute(vq_select_kernel,
                         cudaFuncAttributeMaxDynamicSharedMemorySize, SMEM_BYTES);

    dim3 pgrid(TT / 32, DD / 32, BB);
    dim3 pblk(32, 8);
    vq_prep_x_kernel<<<pgrid, pblk>>>(inputs);
    vq_prep_w_kernel<<<(KK + 255) / 256, 256>>>(weight);

    vq_select_kernel<<<NVEC / 128, 256, SMEM_BYTES>>>();

    int write_idx = (out_size >= QOUT + NVEC) ? 1 : 0;
    // warp per vector: 65536 warps = 8192 blocks x 8 warps
    vq_rescore_kernel<<<NVEC / 8, 256>>>(inputs, weight, out + QOUT, write_idx);

    int gthreads = BB * DD * (TT / 4);
    vq_gather_kernel<<<(gthreads + 255) / 256, 256>>>(weight, out);
}